// round 16
// baseline (speedup 1.0000x reference)
#include <cuda_runtime.h>
#include <cstdint>

// Problem constants
#define BB 8
#define NN 16
#define SS 118
#define AA 10
#define DD 128      // S + A
#define DKK 64
#define HH 2

#define GRID_BLKS 1040   // 16 attention + 1024 noise; all co-resident (8/SM)

// Scratch (no allocations allowed)
__device__ float g_base[BB*HH*NN*DKK];   // base[b,h,i,e]
__device__ float g_diff[BB*HH*NN*DKK];   // (avP-avA)[b,h,j,e]
__device__ float g_nm[BB*HH*NN*NN*DKK];  // mean_k noise[b,h,i,j,k,e]

// Monotonic grid barrier (no per-launch reset; replay-count agnostic).
__device__ unsigned long long g_arrive  = 0ull;
__device__ unsigned long long g_release = 0ull;

// ---------------------------------------------------------------------------
// Threefry2x32 with key = PRNGKey(42) = (0, 42). ks0=0 adds folded out.
// ---------------------------------------------------------------------------
__device__ __forceinline__ void threefry(uint32_t c0, uint32_t c1,
                                         uint32_t& o0, uint32_t& o1) {
  const uint32_t ks1 = 42u;
  const uint32_t ks2 = 42u ^ 0x1BD11BDAu;
  uint32_t x0 = c0;          // + ks0 (=0)
  uint32_t x1 = c1 + ks1;
#define TFR(r) { x0 += x1; x1 = __funnelshift_l(x1, x1, (r)); x1 ^= x0; }
  TFR(13) TFR(15) TFR(26) TFR(6)   x0 += ks1; x1 += ks2 + 1u;
  TFR(17) TFR(29) TFR(16) TFR(24)  x0 += ks2; x1 += 2u;          // + ks0
  TFR(13) TFR(15) TFR(26) TFR(6)   /* x0 += ks0 */ x1 += ks1 + 3u;
  TFR(17) TFR(29) TFR(16) TFR(24)  x0 += ks1; x1 += ks2 + 4u;
  TFR(13) TFR(15) TFR(26) TFR(6)   x0 += ks2; x1 += 5u;          // + ks0
#undef TFR
  o0 = x0; o1 = x1;
}

// Partitionable threefry: bits(idx) = o0 ^ o1 with counter (0, idx).
__device__ __forceinline__ uint32_t tf_mant(uint32_t idx) {
  uint32_t o0, o1;
  threefry(0u, idx, o0, o1);
  return (o0 ^ o1) >> 9;
}

// ---------------------------------------------------------------------------
// Fused kernel: phase A (blocks 0..15 attention, 16..1039 noise),
// grid barrier, phase B (2048 MLP tasks over all 1040 blocks).
// launch_bounds(256,8): 32 regs, smem ~23KB -> guaranteed single wave.
// ---------------------------------------------------------------------------
__global__ void __launch_bounds__(256, 8) k_fused(
    const float* __restrict__ states, const float* __restrict__ policies,
    const float* __restrict__ actions, const float* __restrict__ Wk,
    const float* __restrict__ Wq, const float* __restrict__ Wv,
    const float* __restrict__ W1, const float* __restrict__ W2,
    float* __restrict__ out)
{
  int tid = threadIdx.x;
  int bid = blockIdx.x;

  // shared memory: attention arrays + (reused) MLP buffers
  __shared__ float oa[NN][DD];     // 8 KB
  __shared__ float ptl[NN][AA];    // 0.64 KB
  __shared__ float kb[NN][DKK];    // 4 KB
  __shared__ float qT[DKK][NN];    // 4 KB
  __shared__ float av[NN][DKK];    // 4 KB
  __shared__ float wsm[NN][NN];    // 1 KB
  __shared__ float xs[128];        // MLP x-vector
  __shared__ float part[8];        // MLP warp partials

  if (bid >= 16) {
    // ================= phase A: noise (1 item = 16 hashes per thread) ======
    int item = (bid - 16) * 256 + tid;          // 0..262143
    uint32_t e = (uint32_t)(item & 63);
    uint32_t u = (uint32_t)(item >> 6);         // unit = (b,h,i,j)
    uint32_t cb = u * 1024u + e;
    uint32_t s = 0u;                 // sum of 16 23-bit mantissas < 2^27
#pragma unroll 4
    for (int k = 0; k < 16; ++k)     // 4 independent chains in flight
      s += tf_mant(cb + (uint32_t)(k * 64));
    float fs = fmaf(__uint2float_rn(s), 1.1920929e-7f, 16.0f); // 2^-23
    g_nm[item] = (fs * 0.0625f - 1.5f) * 0.1f;
  } else {
    // ================= phase A: attention for (b,h) ========================
    int b = bid >> 1, h = bid & 1;

    for (int idx = tid; idx < NN * DD; idx += 256) {
      int n = idx >> 7, d = idx & 127;
      oa[n][d] = (d < SS) ? states[(b * NN + n) * SS + d]
                          : actions[(b * NN + n) * AA + (d - SS)];
    }
    if (tid < NN * AA)
      ptl[tid / AA][tid % AA] = policies[(b * NN + tid / AA) * AA + tid % AA];
    __syncthreads();

    int e  = tid & 63;   // output feature
    int ng = tid >> 6;   // row group 0..3

    // K then Q projection (two passes, low register pressure)
    {
      const float4* wk4 = (const float4*)(Wk + (h * 64 + e) * 128);
      float sk[4] = {0,0,0,0};
#pragma unroll 8
      for (int d4 = 0; d4 < 32; ++d4) {
        float4 w = wk4[d4];
#pragma unroll
        for (int t = 0; t < 4; ++t) {
          float4 a = *(const float4*)&oa[ng * 4 + t][d4 * 4];
          sk[t] += a.x * w.x + a.y * w.y + a.z * w.z + a.w * w.w;
        }
      }
#pragma unroll
      for (int t = 0; t < 4; ++t) kb[ng * 4 + t][e] = sk[t];
    }
    {
      const float4* wq4 = (const float4*)(Wq + (h * 64 + e) * 128);
      float sq[4] = {0,0,0,0};
#pragma unroll 8
      for (int d4 = 0; d4 < 32; ++d4) {
        float4 w = wq4[d4];
#pragma unroll
        for (int t = 0; t < 4; ++t) {
          float4 a = *(const float4*)&oa[ng * 4 + t][d4 * 4];
          sq[t] += a.x * w.x + a.y * w.y + a.z * w.z + a.w * w.w;
        }
      }
#pragma unroll
      for (int t = 0; t < 4; ++t) qT[e][ng * 4 + t] = sq[t];
    }
    __syncthreads();

    // scores + parallel softmax: thread (i,j), 16-lane shfl groups
    {
      int i = tid >> 4, j = tid & 15;
      float s = 0.f;
#pragma unroll 16
      for (int ee = 0; ee < 64; ++ee)
        s += kb[i][ee] * qT[ee][j];
      s *= 0.125f;
      float m = s;
#pragma unroll
      for (int o = 8; o > 0; o >>= 1)
        m = fmaxf(m, __shfl_xor_sync(0xffffffffu, m, o, 16));
      float ex = expf(s - m);
      float sum = ex;
#pragma unroll
      for (int o = 8; o > 0; o >>= 1)
        sum += __shfl_xor_sync(0xffffffffu, sum, o, 16);
      float w = ex / sum;
      wsm[i][j] = w;
      out[2048 + ((b * 2 + h) * 16 + i) * 16 + j] = w;   // weight output
    }
    __syncthreads();

    // value projections: sA = oa.Wv; sP = sA + Wv_tail.(pol - act)
    {
      const float4* wv4 = (const float4*)(Wv + (h * 64 + e) * 128);
      const float*  wvt = Wv + (h * 64 + e) * 128 + SS;
      float sA[4] = {0,0,0,0};
#pragma unroll 8
      for (int d4 = 0; d4 < 32; ++d4) {
        float4 wv = wv4[d4];
#pragma unroll
        for (int t = 0; t < 4; ++t) {
          int n = ng * 4 + t;
          float4 a = *(const float4*)&oa[n][d4 * 4];
          sA[t] += a.x * wv.x + a.y * wv.y + a.z * wv.z + a.w * wv.w;
        }
      }
      float wt[10];
#pragma unroll
      for (int d = 0; d < 10; ++d) wt[d] = wvt[d];
#pragma unroll
      for (int t = 0; t < 4; ++t) {
        int n = ng * 4 + t;
        float delta = 0.f;
#pragma unroll
        for (int d = 0; d < 10; ++d)
          delta += wt[d] * (ptl[n][d] - oa[n][SS + d]);
        float ta = tanhf(sA[t]);
        float tp = tanhf(sA[t] + delta);
        av[n][e] = ta;
        g_diff[((b * 2 + h) * 16 + n) * 64 + e] = tp - ta;
      }
    }
    __syncthreads();

    // base[i,e] = sum_k wsm[i][k] * av[k][e]
    for (int o = tid; o < 1024; o += 256) {
      int i = o >> 6, ee = o & 63;
      float s = 0.f;
#pragma unroll
      for (int k = 0; k < 16; ++k)
        s += wsm[i][k] * av[k][ee];
      g_base[((b * 2 + h) * 16 + i) * 64 + ee] = s;
    }
  }

  // ===================== grid barrier (monotonic tickets) ==================
  __syncthreads();                       // all block work done
  if (tid == 0) {
    __threadfence();                     // publish g_nm/g_base/g_diff/weights
    unsigned long long ticket = atomicAdd(&g_arrive, 1ull) + 1ull;
    unsigned long long target =
        ((ticket + (GRID_BLKS - 1)) / GRID_BLKS) * GRID_BLKS;
    if (ticket == target)                // last arriver of this launch
      atomicAdd(&g_release, (unsigned long long)GRID_BLKS);
    // bounded spin: never reached in normal runs; converts a residency
    // failure into a visible wrong-answer instead of a container hang.
    for (long long spin = 0; spin < 200000000LL; ++spin) {
      unsigned long long r;
      asm volatile("ld.volatile.global.u64 %0, [%1];"
                   : "=l"(r) : "l"(&g_release));
      if (r >= target) break;
      __nanosleep(64);
    }
    __threadfence();
  }
  __syncthreads();

  // ===================== phase B: MLP tasks ================================
  // 2048 tasks (b,i,j); block bid takes bid and bid+1040.
  int w = tid >> 5, l = tid & 31;
  for (int task = bid; task < 2048; task += GRID_BLKS) {
    int b = task >> 8, i = (task >> 4) & 15, j = task & 15;

    // assemble x[hd] = (base + w*diff)/16 + noise_mean
    if (tid < 128) {
      int h = tid >> 6, e = tid & 63;
      float ww = out[2048 + ((b * 2 + h) * 16 + i) * 16 + j];
      float bs = g_base[((b * 2 + h) * 16 + i) * 64 + e];
      float df = g_diff[((b * 2 + h) * 16 + j) * 64 + e];
      float nm = g_nm[(((b * 2 + h) * 16 + i) * 16 + j) * 64 + e];
      xs[tid] = (bs + ww * df) * 0.0625f + nm;
    }
    __syncthreads();

    // warp w owns n = w*8..w*8+7; lane l covers cols {l, l+32, l+64, l+96}
    float x0 = xs[l], x1 = xs[l + 32], x2 = xs[l + 64], x3 = xs[l + 96];
    float acc = 0.f;
#pragma unroll
    for (int n8 = 0; n8 < 8; ++n8) {
      int n = w * 8 + n8;
      const float* wr = W1 + n * 128 + l;        // coalesced, L2/L1-hot
      float p = __ldg(wr) * x0 + __ldg(wr + 32) * x1
              + __ldg(wr + 64) * x2 + __ldg(wr + 96) * x3;
#pragma unroll
      for (int o = 16; o > 0; o >>= 1)
        p += __shfl_xor_sync(0xffffffffu, p, o);
      p = p > 0.f ? p : 0.01f * p;               // leaky_relu(0.01)
      acc += p * __ldg(W2 + n);                  // warp-uniform -> broadcast
    }
    if (l == 0) part[w] = acc;
    __syncthreads();
    if (tid == 0) {
      float r = 0.f;
#pragma unroll
      for (int q = 0; q < 8; ++q) r += part[q];
      out[(b * 16 + i) * 16 + j] = r;
    }
    __syncthreads();                     // xs/part reuse safety
  }
}

// ---------------------------------------------------------------------------
extern "C" void kernel_launch(void* const* d_in, const int* in_sizes, int n_in,
                              void* d_out, int out_size) {
  const float* states   = (const float*)d_in[0];
  const float* policies = (const float*)d_in[1];
  const float* actions  = (const float*)d_in[2];
  const float* Wk       = (const float*)d_in[3];
  const float* Wq       = (const float*)d_in[4];
  const float* Wv       = (const float*)d_in[5];
  const float* W1       = (const float*)d_in[6];
  const float* W2       = (const float*)d_in[7];
  float* out = (float*)d_out;

  // single persistent launch; all 1040 blocks co-resident (8/SM x 148 SMs)
  k_fused<<<GRID_BLKS, 256>>>(states, policies, actions,
                              Wk, Wq, Wv, W1, W2, out);
}

// round 17
// speedup vs baseline: 1.1259x; 1.1259x over previous
#include <cuda_runtime.h>
#include <cstdint>

// Problem constants
#define BB 8
#define NN 16
#define SS 118
#define AA 10
#define DD 128      // S + A
#define DKK 64
#define HH 2

// Scratch (no allocations allowed)
__device__ float g_base[BB*HH*NN*DKK];   // base[b,h,i,e]
__device__ float g_diff[BB*HH*NN*DKK];   // (avP-avA)[b,h,j,e]
__device__ float g_nm[BB*HH*NN*NN*DKK];  // mean_k noise[b,h,i,j,k,e]

// Opaque multiplier == 1: prevents ptxas from strength-reducing
// mad.lo.u32(a, one, b) back to IADD3 — keeps the add on the fma pipe.
__device__ volatile uint32_t g_one = 1u;

__device__ __forceinline__ uint32_t ipadd(uint32_t a, uint32_t one, uint32_t b) {
  uint32_t r;
  asm("mad.lo.u32 %0, %1, %2, %3;" : "=r"(r) : "r"(a), "r"(one), "r"(b));
  return r;
}

// ---------------------------------------------------------------------------
// Threefry2x32, key = PRNGKey(42) = (0, 42); ks0=0 folded out.
// Adds on IMAD (fma pipe); rotates/xors on alu pipe -> both pipes carry load.
// ---------------------------------------------------------------------------
__device__ __forceinline__ void threefry(uint32_t one, uint32_t c0, uint32_t c1,
                                         uint32_t& o0, uint32_t& o1) {
  const uint32_t ks1 = 42u;
  const uint32_t ks2 = 42u ^ 0x1BD11BDAu;
  uint32_t x0 = c0;          // + ks0 (=0)
  uint32_t x1 = ipadd(c1, one, ks1);
#define TFR(r) { x0 = ipadd(x0, one, x1); x1 = __funnelshift_l(x1, x1, (r)); x1 ^= x0; }
  TFR(13) TFR(15) TFR(26) TFR(6)
  x0 = ipadd(x0, one, ks1); x1 = ipadd(x1, one, ks2 + 1u);
  TFR(17) TFR(29) TFR(16) TFR(24)
  x0 = ipadd(x0, one, ks2); x1 = ipadd(x1, one, 2u);           // + ks0
  TFR(13) TFR(15) TFR(26) TFR(6)
  /* x0 += ks0 */           x1 = ipadd(x1, one, ks1 + 3u);
  TFR(17) TFR(29) TFR(16) TFR(24)
  x0 = ipadd(x0, one, ks1); x1 = ipadd(x1, one, ks2 + 4u);
  TFR(13) TFR(15) TFR(26) TFR(6)
  x0 = ipadd(x0, one, ks2); x1 = ipadd(x1, one, 5u);           // + ks0
#undef TFR
  o0 = x0; o1 = x1;
}

// Partitionable threefry: bits(idx) = o0 ^ o1 with counter (0, idx).
__device__ __forceinline__ uint32_t tf_mant(uint32_t one, uint32_t idx) {
  uint32_t o0, o1;
  threefry(one, 0u, idx, o0, o1);
  return (o0 ^ o1) >> 9;
}

// ---------------------------------------------------------------------------
// Stage 1: blocks 0..15     -> attention math per (b,h), ~22KB smem
//          blocks 16..1039  -> noise: exactly 1 item (16 hashes) per thread
// smem <= 22KB + launch_bounds(256,8) -> 8 blocks/SM -> single resident wave.
// ---------------------------------------------------------------------------
__global__ void __launch_bounds__(256, 8) k_stage1(
    const float* __restrict__ states, const float* __restrict__ policies,
    const float* __restrict__ actions, const float* __restrict__ Wk,
    const float* __restrict__ Wq, const float* __restrict__ Wv,
    float* __restrict__ out)
{
  int tid = threadIdx.x;

  if (blockIdx.x >= 16) {
    uint32_t one = g_one;                       // opaque 1 (L1-hot broadcast)
    int item = (blockIdx.x - 16) * 256 + tid;   // 0..262143
    uint32_t e = (uint32_t)(item & 63);
    uint32_t u = (uint32_t)(item >> 6);         // unit = (b,h,i,j)
    uint32_t cb = u * 1024u + e;
    uint32_t s = 0u;                 // sum of 16 23-bit mantissas < 2^27
#pragma unroll 4
    for (int k = 0; k < 16; ++k)     // 4 independent chains in flight
      s += tf_mant(one, cb + (uint32_t)(k * 64));
    float fs = fmaf(__uint2float_rn(s), 1.1920929e-7f, 16.0f); // 2^-23
    g_nm[item] = (fs * 0.0625f - 1.5f) * 0.1f;
    return;
  }

  // ---------------- attention math for (b,h) ----------------
  int b = blockIdx.x >> 1, h = blockIdx.x & 1;
  __shared__ float oa[NN][DD];     // 8 KB
  __shared__ float ptl[NN][AA];    // 0.64 KB (policy tail only)
  __shared__ float kb[NN][DKK];    // 4 KB
  __shared__ float qT[DKK][NN];    // 4 KB
  __shared__ float av[NN][DKK];    // 4 KB
  __shared__ float wsm[NN][NN];    // 1 KB

  for (int idx = tid; idx < NN * DD; idx += 256) {
    int n = idx >> 7, d = idx & 127;
    oa[n][d] = (d < SS) ? states[(b * NN + n) * SS + d]
                        : actions[(b * NN + n) * AA + (d - SS)];
  }
  if (tid < NN * AA)
    ptl[tid / AA][tid % AA] = policies[(b * NN + tid / AA) * AA + tid % AA];
  __syncthreads();

  int e  = tid & 63;   // output feature
  int ng = tid >> 6;   // row group 0..3

  // K then Q projection (two passes, low register pressure)
  {
    const float4* wk4 = (const float4*)(Wk + (h * 64 + e) * 128);
    float sk[4] = {0,0,0,0};
#pragma unroll 8
    for (int d4 = 0; d4 < 32; ++d4) {
      float4 w = wk4[d4];
#pragma unroll
      for (int t = 0; t < 4; ++t) {
        float4 a = *(const float4*)&oa[ng * 4 + t][d4 * 4];
        sk[t] += a.x * w.x + a.y * w.y + a.z * w.z + a.w * w.w;
      }
    }
#pragma unroll
    for (int t = 0; t < 4; ++t) kb[ng * 4 + t][e] = sk[t];
  }
  {
    const float4* wq4 = (const float4*)(Wq + (h * 64 + e) * 128);
    float sq[4] = {0,0,0,0};
#pragma unroll 8
    for (int d4 = 0; d4 < 32; ++d4) {
      float4 w = wq4[d4];
#pragma unroll
      for (int t = 0; t < 4; ++t) {
        float4 a = *(const float4*)&oa[ng * 4 + t][d4 * 4];
        sq[t] += a.x * w.x + a.y * w.y + a.z * w.z + a.w * w.w;
      }
    }
#pragma unroll
    for (int t = 0; t < 4; ++t) qT[e][ng * 4 + t] = sq[t];
  }
  __syncthreads();

  // scores + parallel softmax: thread (i,j), 16-lane shfl groups
  {
    int i = tid >> 4, j = tid & 15;
    float s = 0.f;
#pragma unroll 16
    for (int ee = 0; ee < 64; ++ee)
      s += kb[i][ee] * qT[ee][j];
    s *= 0.125f;
    float m = s;
#pragma unroll
    for (int o = 8; o > 0; o >>= 1)
      m = fmaxf(m, __shfl_xor_sync(0xffffffffu, m, o, 16));
    float ex = expf(s - m);
    float sum = ex;
#pragma unroll
    for (int o = 8; o > 0; o >>= 1)
      sum += __shfl_xor_sync(0xffffffffu, sum, o, 16);
    float w = ex / sum;
    wsm[i][j] = w;
    out[2048 + ((b * 2 + h) * 16 + i) * 16 + j] = w;     // weight output
  }
  __syncthreads();

  // value projections: sA = oa.Wv; sP = sA + Wv_tail.(pol - act)
  {
    const float4* wv4 = (const float4*)(Wv + (h * 64 + e) * 128);
    const float*  wvt = Wv + (h * 64 + e) * 128 + SS;
    float sA[4] = {0,0,0,0};
#pragma unroll 8
    for (int d4 = 0; d4 < 32; ++d4) {
      float4 wv = wv4[d4];
#pragma unroll
      for (int t = 0; t < 4; ++t) {
        int n = ng * 4 + t;
        float4 a = *(const float4*)&oa[n][d4 * 4];
        sA[t] += a.x * wv.x + a.y * wv.y + a.z * wv.z + a.w * wv.w;
      }
    }
    float wt[10];
#pragma unroll
    for (int d = 0; d < 10; ++d) wt[d] = wvt[d];
#pragma unroll
    for (int t = 0; t < 4; ++t) {
      int n = ng * 4 + t;
      float delta = 0.f;
#pragma unroll
      for (int d = 0; d < 10; ++d)
        delta += wt[d] * (ptl[n][d] - oa[n][SS + d]);
      float ta = tanhf(sA[t]);
      float tp = tanhf(sA[t] + delta);
      av[n][e] = ta;
      g_diff[((b * 2 + h) * 16 + n) * 64 + e] = tp - ta;
    }
  }
  __syncthreads();

  // base[i,e] = sum_k wsm[i][k] * av[k][e]
  for (int o = tid; o < 1024; o += 256) {
    int i = o >> 6, ee = o & 63;
    float s = 0.f;
#pragma unroll
    for (int k = 0; k < 16; ++k)
      s += wsm[i][k] * av[k][ee];
    g_base[((b * 2 + h) * 16 + i) * 64 + ee] = s;
  }
}

// ---------------------------------------------------------------------------
// Final: block per (b,i,jq), 4 j's. Warp w owns rows n = w*8..w*8+7; lane l
// covers cols {l,l+32,l+64,l+96} (W1 coalesced, L2-hot). All 8 dots per warp
// are reduced SIMULTANEOUSLY by a split butterfly (offsets 16/8/4 halve the
// value set: 4+2+1 shfls; offsets 1,2 finish) -> 12 shfl/jj vs 45 before.
// After the reduce, lane l holds the full dot for n8 = (l>>2)&7.
// ---------------------------------------------------------------------------
__global__ void __launch_bounds__(256) k_final(
    const float* __restrict__ W1, const float* __restrict__ W2,
    float* __restrict__ out)
{
  int blk = blockIdx.x;                 // 0..511
  int b = blk >> 6, i = (blk >> 2) & 15, jq = blk & 3;
  int t = threadIdx.x;
  int w = t >> 5, l = t & 31;

  __shared__ float xs[4][128];
  __shared__ float w2s[64];
  __shared__ float part[4][8];          // [jj][warp]

  if (t < 64) w2s[t] = W2[t];

  // assemble x[jj][hd] = (base + w*diff)/16 + noise_mean   for 4 j's
  for (int idx = t; idx < 512; idx += 256) {
    int jj = idx >> 7, hd = idx & 127;
    int j = jq * 4 + jj, h = hd >> 6, e = hd & 63;
    float ww = out[2048 + ((b * 2 + h) * 16 + i) * 16 + j];
    float bs = g_base[((b * 2 + h) * 16 + i) * 64 + e];
    float df = g_diff[((b * 2 + h) * 16 + j) * 64 + e];
    float nm = g_nm[(((b * 2 + h) * 16 + i) * 16 + j) * 64 + e];
    xs[jj][hd] = (bs + ww * df) * 0.0625f + nm;
  }
  __syncthreads();

  float xr[4][4];
#pragma unroll
  for (int jj = 0; jj < 4; ++jj)
#pragma unroll
    for (int k = 0; k < 4; ++k)
      xr[jj][k] = xs[jj][l + 32 * k];

  // partial dots: acc[jj][n8], W1 loads hoisted across jj
  float acc[4][8];
#pragma unroll
  for (int n8 = 0; n8 < 8; ++n8) {
    const float* wr = W1 + (w * 8 + n8) * 128 + l;
    float w0 = __ldg(wr);
    float w1 = __ldg(wr + 32);
    float w2 = __ldg(wr + 64);
    float w3 = __ldg(wr + 96);
#pragma unroll
    for (int jj = 0; jj < 4; ++jj)
      acc[jj][n8] = w0 * xr[jj][0] + w1 * xr[jj][1]
                  + w2 * xr[jj][2] + w3 * xr[jj][3];
  }

  int n_mine = w * 8 + ((l >> 2) & 7);
  float w2n = w2s[n_mine];
  bool b16 = (l & 16) != 0;
  bool b8  = (l & 8)  != 0;
  bool b4  = (l & 4)  != 0;

#pragma unroll
  for (int jj = 0; jj < 4; ++jj) {
    float* a = acc[jj];
    // level 16: 8 -> 4 values
#pragma unroll
    for (int m = 0; m < 4; ++m) {
      float send = b16 ? a[m] : a[m + 4];
      float keep = b16 ? a[m + 4] : a[m];
      a[m] = keep + __shfl_xor_sync(0xffffffffu, send, 16);
    }
    // level 8: 4 -> 2
#pragma unroll
    for (int m = 0; m < 2; ++m) {
      float send = b8 ? a[m] : a[m + 2];
      float keep = b8 ? a[m + 2] : a[m];
      a[m] = keep + __shfl_xor_sync(0xffffffffu, send, 8);
    }
    // level 4: 2 -> 1
    {
      float send = b4 ? a[0] : a[1];
      float keep = b4 ? a[1] : a[0];
      a[0] = keep + __shfl_xor_sync(0xffffffffu, send, 4);
    }
    // finish: 4 lanes per n8 hold disjoint partials
    a[0] += __shfl_xor_sync(0xffffffffu, a[0], 1);
    a[0] += __shfl_xor_sync(0xffffffffu, a[0], 2);
    // lane l: full dot for n = n_mine
    float y = a[0] > 0.f ? a[0] : 0.01f * a[0];  // leaky_relu(0.01)
    float r = y * w2n;
    // sum over the 8 distinct n8 in the warp (each counted once)
    r += __shfl_xor_sync(0xffffffffu, r, 4);
    r += __shfl_xor_sync(0xffffffffu, r, 8);
    r += __shfl_xor_sync(0xffffffffu, r, 16);
    if (l == 0) part[jj][w] = r;
  }
  __syncthreads();
  if (t < 4) {
    float r = 0.f;
#pragma unroll
    for (int q = 0; q < 8; ++q) r += part[t][q];
    out[(b * 16 + i) * 16 + jq * 4 + t] = r;
  }
}

// ---------------------------------------------------------------------------
extern "C" void kernel_launch(void* const* d_in, const int* in_sizes, int n_in,
                              void* d_out, int out_size) {
  const float* states   = (const float*)d_in[0];
  const float* policies = (const float*)d_in[1];
  const float* actions  = (const float*)d_in[2];
  const float* Wk       = (const float*)d_in[3];
  const float* Wq       = (const float*)d_in[4];
  const float* Wv       = (const float*)d_in[5];
  const float* W1       = (const float*)d_in[6];
  const float* W2       = (const float*)d_in[7];
  float* out = (float*)d_out;

  k_stage1<<<1040, 256>>>(states, policies, actions, Wk, Wq, Wv, out);
  k_final<<<512, 256>>>(W1, W2, out);
}